// round 1
// baseline (speedup 1.0000x reference)
#include <cuda_runtime.h>

// Problem constants
#define B_    2
#define T_    2048
#define C_    2048
#define NH_   16
#define HS_   128
#define NLQ_  512
#define NLKV_ 512
#define DHR_  64

// Static scratch (allocation-free rule: __device__ globals)
__device__ float g_cq  [B_*T_*NLQ_];            //  8 MB
__device__ float g_ckv [B_*T_*NLKV_];           //  8 MB
__device__ float g_keff[NH_*NLQ_*NLKV_];        // 16 MB
__device__ float g_Rt  [C_*NLKV_];              //  4 MB  (Rt[c,k] = (W_o @ W_uv)[c,k])
__device__ float g_qc  [B_*NH_*T_*NLKV_];       // 128 MB
__device__ float g_cqr [B_*T_*NH_*DHR_];        // 16 MB
__device__ float g_qr  [B_*T_*NH_*DHR_];        // 16 MB
__device__ float g_ckr [B_*T_*DHR_];            //  1 MB
__device__ float g_kr  [B_*T_*DHR_];            //  1 MB
__device__ float g_S   [134217728];             // 512 MB  [B,NH,T,T]
__device__ float g_ctx [B_*NH_*T_*NLKV_];       // 128 MB

// ----------------------------------------------------------------------------
// Generic batched SGEMM: C[m,n] (+)= sum_k A[m,k] * B'[k,n]
//   B' = B (row-major [K,N], ldb) if BT==0, else B^T with B row-major [N,K].
//   Batch z -> (bb = z/HB, hh = z%HB); per-matrix offsets bb*s?b + hh*s?h.
//   Tiles: 64x64x16, 256 threads, 4x4 micro-tile. Requires M%64==0, N%64==0,
//   K%16==0, all ld/strides %4==0 (true for every call below).
// ----------------------------------------------------------------------------
__global__ void sgemm64(const float* __restrict__ A, const float* __restrict__ B,
                        float* __restrict__ C,
                        int M, int N, int K, int lda, int ldb, int ldc,
                        int HB,
                        long long sAb, long long sAh,
                        long long sBb, long long sBh,
                        long long sCb, long long sCh,
                        int BT, int accum)
{
    const int z  = blockIdx.z;
    const int bb = z / HB, hh = z - bb * HB;
    A += bb * sAb + hh * sAh;
    B += bb * sBb + hh * sBh;
    C += bb * sCb + hh * sCh;

    const int row0 = blockIdx.y * 64;
    const int col0 = blockIdx.x * 64;

    __shared__ float As[16][68];
    __shared__ float Bs[16][68];

    const int tid = threadIdx.x;
    const int tx  = tid & 15;
    const int ty  = tid >> 4;

    // A (and BT-B) loader: 64 rows x 16 k, one float4 per thread
    const int ar = tid >> 2;          // 0..63
    const int ak = (tid & 3) * 4;     // 0,4,8,12
    // NN-B loader: 16 k x 64 n
    const int bk = tid >> 4;          // 0..15
    const int bn = (tid & 15) * 4;    // 0..60

    float acc[4][4] = {};

    for (int k0 = 0; k0 < K; k0 += 16) {
        float4 av = *(const float4*)(A + (long long)(row0 + ar) * lda + (k0 + ak));
        As[ak + 0][ar] = av.x;
        As[ak + 1][ar] = av.y;
        As[ak + 2][ar] = av.z;
        As[ak + 3][ar] = av.w;

        if (BT) {
            float4 bv = *(const float4*)(B + (long long)(col0 + ar) * ldb + (k0 + ak));
            Bs[ak + 0][ar] = bv.x;
            Bs[ak + 1][ar] = bv.y;
            Bs[ak + 2][ar] = bv.z;
            Bs[ak + 3][ar] = bv.w;
        } else {
            float4 bv = *(const float4*)(B + (long long)(k0 + bk) * ldb + (col0 + bn));
            *(float4*)&Bs[bk][bn] = bv;
        }
        __syncthreads();

        #pragma unroll
        for (int kk = 0; kk < 16; kk++) {
            float4 a4 = *(const float4*)&As[kk][ty * 4];
            float4 b4 = *(const float4*)&Bs[kk][tx * 4];
            float aa[4] = {a4.x, a4.y, a4.z, a4.w};
            float bbv[4] = {b4.x, b4.y, b4.z, b4.w};
            #pragma unroll
            for (int i = 0; i < 4; i++)
                #pragma unroll
                for (int j = 0; j < 4; j++)
                    acc[i][j] += aa[i] * bbv[j];
        }
        __syncthreads();
    }

    #pragma unroll
    for (int i = 0; i < 4; i++) {
        #pragma unroll
        for (int j = 0; j < 4; j++) {
            long long off = (long long)(row0 + ty * 4 + i) * ldc + (col0 + tx * 4 + j);
            if (accum) C[off] += acc[i][j];
            else       C[off]  = acc[i][j];
        }
    }
}

// ----------------------------------------------------------------------------
// RoPE for q: in/out layout [B,T,NH,DHR] flat; pair j = ((b*T+t)*NH+h)*32 + i
// ----------------------------------------------------------------------------
__global__ void rope_q_kernel(const float* __restrict__ in, float* __restrict__ out,
                              const float* __restrict__ cosp, const float* __restrict__ sinp)
{
    int j = blockIdx.x * blockDim.x + threadIdx.x;
    if (j >= B_ * T_ * NH_ * (DHR_ / 2)) return;
    int i = j & 31;
    int t = (j >> 9) % T_;              // j / (NH*32) % T
    float c = cosp[t * 32 + i];
    float s = sinp[t * 32 + i];
    float re = in[2 * j], im = in[2 * j + 1];
    out[2 * j]     = re * c - im * s;
    out[2 * j + 1] = re * s + im * c;
}

// RoPE for k: layout [B,T,DHR]; pair j = (b*T+t)*32 + i
__global__ void rope_k_kernel(const float* __restrict__ in, float* __restrict__ out,
                              const float* __restrict__ cosp, const float* __restrict__ sinp)
{
    int j = blockIdx.x * blockDim.x + threadIdx.x;
    if (j >= B_ * T_ * (DHR_ / 2)) return;
    int i = j & 31;
    int t = (j >> 5) % T_;
    float c = cosp[t * 32 + i];
    float s = sinp[t * 32 + i];
    float re = in[2 * j], im = in[2 * j + 1];
    out[2 * j]     = re * c - im * s;
    out[2 * j + 1] = re * s + im * c;
}

// ----------------------------------------------------------------------------
// Causal softmax with scale, in-place on S rows of length T_. One block/row.
// Row index = b*NH*T + h*T + t ; valid cols [0, t]; tail zeroed.
// ----------------------------------------------------------------------------
__global__ void softmax_causal_kernel(float* __restrict__ S)
{
    const float scale = 0.07216878364870323f;   // 1/sqrt(HS+DHR) = 1/sqrt(192)
    long long row = blockIdx.x;
    int t = (int)(row % T_);
    float* p = S + row * (long long)T_;
    int tid = threadIdx.x;

    float v[8];
    float m = -3.0e38f;
    #pragma unroll
    for (int j = 0; j < 8; j++) {
        int i = tid + j * 256;
        float x = (i <= t) ? p[i] * scale : -3.0e38f;
        v[j] = x;
        m = fmaxf(m, x);
    }

    __shared__ float red[256];
    red[tid] = m;
    __syncthreads();
    for (int s = 128; s > 0; s >>= 1) {
        if (tid < s) red[tid] = fmaxf(red[tid], red[tid + s]);
        __syncthreads();
    }
    m = red[0];
    __syncthreads();

    float sum = 0.f;
    #pragma unroll
    for (int j = 0; j < 8; j++) {
        int i = tid + j * 256;
        float e = (i <= t) ? __expf(v[j] - m) : 0.f;
        v[j] = e;
        sum += e;
    }
    red[tid] = sum;
    __syncthreads();
    for (int s = 128; s > 0; s >>= 1) {
        if (tid < s) red[tid] += red[tid + s];
        __syncthreads();
    }
    float inv = 1.0f / red[0];

    #pragma unroll
    for (int j = 0; j < 8; j++) {
        int i = tid + j * 256;
        p[i] = v[j] * inv;
    }
}

// ----------------------------------------------------------------------------
// Host launcher
// ----------------------------------------------------------------------------
static inline void launch_gemm(const float* A, const float* B, float* C,
                               int M, int N, int K, int lda, int ldb, int ldc,
                               int batches, int HB,
                               long long sAb, long long sAh,
                               long long sBb, long long sBh,
                               long long sCb, long long sCh,
                               int BT, int accum)
{
    dim3 grid(N / 64, M / 64, batches);
    sgemm64<<<grid, 256>>>(A, B, C, M, N, K, lda, ldb, ldc, HB,
                           sAb, sAh, sBb, sBh, sCb, sCh, BT, accum);
}

extern "C" void kernel_launch(void* const* d_in, const int* in_sizes, int n_in,
                              void* d_out, int out_size)
{
    (void)in_sizes; (void)n_in; (void)out_size;
    const float* x     = (const float*)d_in[0];
    const float* cosp  = (const float*)d_in[1];
    const float* sinp  = (const float*)d_in[2];
    const float* W_dq  = (const float*)d_in[3];
    const float* W_uq  = (const float*)d_in[4];
    const float* W_dkv = (const float*)d_in[5];
    const float* W_uk  = (const float*)d_in[6];
    const float* W_uv  = (const float*)d_in[7];
    const float* W_qr  = (const float*)d_in[8];
    const float* W_kr  = (const float*)d_in[9];
    const float* W_o   = (const float*)d_in[10];
    float* y = (float*)d_out;

    float *cq, *ckv, *keff, *Rt, *qc, *cqr, *qr, *ckr, *kr, *S, *ctx;
    cudaGetSymbolAddress((void**)&cq,   g_cq);
    cudaGetSymbolAddress((void**)&ckv,  g_ckv);
    cudaGetSymbolAddress((void**)&keff, g_keff);
    cudaGetSymbolAddress((void**)&Rt,   g_Rt);
    cudaGetSymbolAddress((void**)&qc,   g_qc);
    cudaGetSymbolAddress((void**)&cqr,  g_cqr);
    cudaGetSymbolAddress((void**)&qr,   g_qr);
    cudaGetSymbolAddress((void**)&ckr,  g_ckr);
    cudaGetSymbolAddress((void**)&kr,   g_kr);
    cudaGetSymbolAddress((void**)&S,    g_S);
    cudaGetSymbolAddress((void**)&ctx,  g_ctx);

    const long long TT   = (long long)T_ * T_;          // 4194304
    const long long T512 = (long long)T_ * 512;         // 1048576

    // 1) c_q = x @ W_dq^T     [4096,512]
    launch_gemm(x, W_dq, cq, B_*T_, NLQ_, C_, C_, C_, NLQ_,
                1, 1, 0,0, 0,0, 0,0, /*BT=*/1, 0);
    // 2) c_kv = x @ W_dkv^T   [4096,512]
    launch_gemm(x, W_dkv, ckv, B_*T_, NLKV_, C_, C_, C_, NLKV_,
                1, 1, 0,0, 0,0, 0,0, 1, 0);
    // 3) k_eff[h] = W_uq_r[:,h,:] @ W_uk_r[h]   (16 batched, M=512,N=512,K=128)
    launch_gemm(W_uq, W_uk, keff, NLQ_, NLKV_, HS_, C_, NLKV_, NLKV_,
                NH_, NH_, 0, HS_, 0, (long long)HS_*NLKV_, 0, (long long)NLQ_*NLKV_, 0, 0);
    // 4) Rt = W_o @ W_uv      [2048,512]
    launch_gemm(W_o, W_uv, Rt, C_, NLKV_, C_, C_, NLKV_, NLKV_,
                1, 1, 0,0, 0,0, 0,0, 0, 0);
    // 5) q_c[b,h] = c_q[b] @ k_eff[h]   (32 batched, M=2048,N=512,K=512)
    launch_gemm(cq, keff, qc, T_, NLKV_, NLQ_, NLQ_, NLKV_, NLKV_,
                B_*NH_, NH_, T512, 0, 0, (long long)NLQ_*NLKV_, (long long)NH_*T512, T512, 0, 0);
    // 6) c_qr = c_q @ W_qr^T   [4096,1024]
    launch_gemm(cq, W_qr, cqr, B_*T_, NH_*DHR_, NLQ_, NLQ_, NLQ_, NH_*DHR_,
                1, 1, 0,0, 0,0, 0,0, 1, 0);
    // 7) q_r = rope(c_qr)
    {
        int n = B_ * T_ * NH_ * (DHR_ / 2);
        rope_q_kernel<<<(n + 255) / 256, 256>>>(cqr, qr, cosp, sinp);
    }
    // 8) c_kr = x @ W_kr^T     [4096,64]
    launch_gemm(x, W_kr, ckr, B_*T_, DHR_, C_, C_, C_, DHR_,
                1, 1, 0,0, 0,0, 0,0, 1, 0);
    // 9) k_r = rope(c_kr)
    {
        int n = B_ * T_ * (DHR_ / 2);
        rope_k_kernel<<<(n + 255) / 256, 256>>>(ckr, kr, cosp, sinp);
    }
    // 10) S = q_c @ c_kv^T     (32 batched, M=2048,N=2048,K=512)
    launch_gemm(qc, ckv, S, T_, T_, NLKV_, NLKV_, NLKV_, T_,
                B_*NH_, NH_, (long long)NH_*T512, T512, T512, 0,
                (long long)NH_*TT, TT, 1, 0);
    // 11) S += q_r @ k_r^T     (32 batched, M=2048,N=2048,K=64; A row stride 1024)
    launch_gemm(qr, kr, S, T_, T_, DHR_, NH_*DHR_, DHR_, T_,
                B_*NH_, NH_, (long long)T_*NH_*DHR_, DHR_, (long long)T_*DHR_, 0,
                (long long)NH_*TT, TT, 1, 1);
    // 12) causal softmax in place
    softmax_causal_kernel<<<B_*NH_*T_, 256>>>(S);
    // 13) ctx = P @ c_kv       (32 batched, M=2048,N=512,K=2048)
    launch_gemm(S, ckv, ctx, T_, NLKV_, T_, T_, NLKV_, NLKV_,
                B_*NH_, NH_, (long long)NH_*TT, TT, T512, 0,
                (long long)NH_*T512, T512, 0, 0);
    // 14) y[b,t,h*128+d] = ctx[b,h] @ Rt[h*128: , :]^T   (32 batched, M=2048,N=128,K=512)
    launch_gemm(ctx, Rt, y, T_, HS_, NLKV_, NLKV_, NLKV_, C_,
                B_*NH_, NH_, (long long)NH_*T512, T512, 0, (long long)HS_*NLKV_,
                (long long)T_*C_, HS_, 1, 0);
}

// round 2
// speedup vs baseline: 1.0011x; 1.0011x over previous
#include <cuda_runtime.h>

// Problem constants
#define B_    2
#define T_    2048
#define C_    2048
#define NH_   16
#define HS_   128
#define NLQ_  512
#define NLKV_ 512
#define DHR_  64

// Static scratch (allocation-free rule: __device__ globals)
__device__ float g_cq  [B_*T_*NLQ_];            //  8 MB
__device__ float g_ckv [B_*T_*NLKV_];           //  8 MB
__device__ float g_keff[NH_*NLQ_*NLKV_];        // 16 MB
__device__ float g_Rt  [C_*NLKV_];              //  4 MB  (Rt[c,k] = (W_o @ W_uv)[c,k])
__device__ float g_qc  [B_*NH_*T_*NLKV_];       // 128 MB
__device__ float g_cqr [B_*T_*NH_*DHR_];        // 16 MB
__device__ float g_qr  [B_*T_*NH_*DHR_];        // 16 MB
__device__ float g_ckr [B_*T_*DHR_];            //  1 MB
__device__ float g_kr  [B_*T_*DHR_];            //  1 MB
__device__ float g_S   [134217728];             // 512 MB  [B,NH,T,T]
__device__ float g_ctx [B_*NH_*T_*NLKV_];       // 128 MB

// ----------------------------------------------------------------------------
// Generic batched SGEMM: C[m,n] (+)= sum_k A[m,k] * B'[k,n]
//   B' = B (row-major [K,N], ldb) if BT==0, else B^T with B row-major [N,K].
//   Batch z -> (bb = z/HB, hh = z%HB); per-matrix offsets bb*s?b + hh*s?h.
//   Tiles: 64x64x16, 256 threads, 4x4 micro-tile. Requires M%64==0, N%64==0,
//   K%16==0, all ld/strides %4==0 (true for every call below).
// ----------------------------------------------------------------------------
__global__ void sgemm64(const float* __restrict__ A, const float* __restrict__ B,
                        float* __restrict__ C,
                        int M, int N, int K, int lda, int ldb, int ldc,
                        int HB,
                        long long sAb, long long sAh,
                        long long sBb, long long sBh,
                        long long sCb, long long sCh,
                        int BT, int accum)
{
    const int z  = blockIdx.z;
    const int bb = z / HB, hh = z - bb * HB;
    A += bb * sAb + hh * sAh;
    B += bb * sBb + hh * sBh;
    C += bb * sCb + hh * sCh;

    const int row0 = blockIdx.y * 64;
    const int col0 = blockIdx.x * 64;

    __shared__ float As[16][68];
    __shared__ float Bs[16][68];

    const int tid = threadIdx.x;
    const int tx  = tid & 15;
    const int ty  = tid >> 4;

    // A (and BT-B) loader: 64 rows x 16 k, one float4 per thread
    const int ar = tid >> 2;          // 0..63
    const int ak = (tid & 3) * 4;     // 0,4,8,12
    // NN-B loader: 16 k x 64 n
    const int bk = tid >> 4;          // 0..15
    const int bn = (tid & 15) * 4;    // 0..60

    float acc[4][4] = {};

    for (int k0 = 0; k0 < K; k0 += 16) {
        float4 av = *(const float4*)(A + (long long)(row0 + ar) * lda + (k0 + ak));
        As[ak + 0][ar] = av.x;
        As[ak + 1][ar] = av.y;
        As[ak + 2][ar] = av.z;
        As[ak + 3][ar] = av.w;

        if (BT) {
            float4 bv = *(const float4*)(B + (long long)(col0 + ar) * ldb + (k0 + ak));
            Bs[ak + 0][ar] = bv.x;
            Bs[ak + 1][ar] = bv.y;
            Bs[ak + 2][ar] = bv.z;
            Bs[ak + 3][ar] = bv.w;
        } else {
            float4 bv = *(const float4*)(B + (long long)(k0 + bk) * ldb + (col0 + bn));
            *(float4*)&Bs[bk][bn] = bv;
        }
        __syncthreads();

        #pragma unroll
        for (int kk = 0; kk < 16; kk++) {
            float4 a4 = *(const float4*)&As[kk][ty * 4];
            float4 b4 = *(const float4*)&Bs[kk][tx * 4];
            float aa[4] = {a4.x, a4.y, a4.z, a4.w};
            float bbv[4] = {b4.x, b4.y, b4.z, b4.w};
            #pragma unroll
            for (int i = 0; i < 4; i++)
                #pragma unroll
                for (int j = 0; j < 4; j++)
                    acc[i][j] += aa[i] * bbv[j];
        }
        __syncthreads();
    }

    #pragma unroll
    for (int i = 0; i < 4; i++) {
        #pragma unroll
        for (int j = 0; j < 4; j++) {
            long long off = (long long)(row0 + ty * 4 + i) * ldc + (col0 + tx * 4 + j);
            if (accum) C[off] += acc[i][j];
            else       C[off]  = acc[i][j];
        }
    }
}

// ----------------------------------------------------------------------------
// RoPE for q: in/out layout [B,T,NH,DHR] flat; pair j = ((b*T+t)*NH+h)*32 + i
// ----------------------------------------------------------------------------
__global__ void rope_q_kernel(const float* __restrict__ in, float* __restrict__ out,
                              const float* __restrict__ cosp, const float* __restrict__ sinp)
{
    int j = blockIdx.x * blockDim.x + threadIdx.x;
    if (j >= B_ * T_ * NH_ * (DHR_ / 2)) return;
    int i = j & 31;
    int t = (j >> 9) % T_;              // j / (NH*32) % T
    float c = cosp[t * 32 + i];
    float s = sinp[t * 32 + i];
    float re = in[2 * j], im = in[2 * j + 1];
    out[2 * j]     = re * c - im * s;
    out[2 * j + 1] = re * s + im * c;
}

// RoPE for k: layout [B,T,DHR]; pair j = (b*T+t)*32 + i
__global__ void rope_k_kernel(const float* __restrict__ in, float* __restrict__ out,
                              const float* __restrict__ cosp, const float* __restrict__ sinp)
{
    int j = blockIdx.x * blockDim.x + threadIdx.x;
    if (j >= B_ * T_ * (DHR_ / 2)) return;
    int i = j & 31;
    int t = (j >> 5) % T_;
    float c = cosp[t * 32 + i];
    float s = sinp[t * 32 + i];
    float re = in[2 * j], im = in[2 * j + 1];
    out[2 * j]     = re * c - im * s;
    out[2 * j + 1] = re * s + im * c;
}

// ----------------------------------------------------------------------------
// Causal softmax with scale, in-place on S rows of length T_. One block/row.
// Row index = b*NH*T + h*T + t ; valid cols [0, t]; tail zeroed.
// ----------------------------------------------------------------------------
__global__ void softmax_causal_kernel(float* __restrict__ S)
{
    const float scale = 0.07216878364870323f;   // 1/sqrt(HS+DHR) = 1/sqrt(192)
    long long row = blockIdx.x;
    int t = (int)(row % T_);
    float* p = S + row * (long long)T_;
    int tid = threadIdx.x;

    float v[8];
    float m = -3.0e38f;
    #pragma unroll
    for (int j = 0; j < 8; j++) {
        int i = tid + j * 256;
        float x = (i <= t) ? p[i] * scale : -3.0e38f;
        v[j] = x;
        m = fmaxf(m, x);
    }

    __shared__ float red[256];
    red[tid] = m;
    __syncthreads();
    for (int s = 128; s > 0; s >>= 1) {
        if (tid < s) red[tid] = fmaxf(red[tid], red[tid + s]);
        __syncthreads();
    }
    m = red[0];
    __syncthreads();

    float sum = 0.f;
    #pragma unroll
    for (int j = 0; j < 8; j++) {
        int i = tid + j * 256;
        float e = (i <= t) ? __expf(v[j] - m) : 0.f;
        v[j] = e;
        sum += e;
    }
    red[tid] = sum;
    __syncthreads();
    for (int s = 128; s > 0; s >>= 1) {
        if (tid < s) red[tid] += red[tid + s];
        __syncthreads();
    }
    float inv = 1.0f / red[0];

    #pragma unroll
    for (int j = 0; j < 8; j++) {
        int i = tid + j * 256;
        p[i] = v[j] * inv;
    }
}

// ----------------------------------------------------------------------------
// Host launcher
// ----------------------------------------------------------------------------
static inline void launch_gemm(const float* A, const float* B, float* C,
                               int M, int N, int K, int lda, int ldb, int ldc,
                               int batches, int HB,
                               long long sAb, long long sAh,
                               long long sBb, long long sBh,
                               long long sCb, long long sCh,
                               int BT, int accum)
{
    dim3 grid(N / 64, M / 64, batches);
    sgemm64<<<grid, 256>>>(A, B, C, M, N, K, lda, ldb, ldc, HB,
                           sAb, sAh, sBb, sBh, sCb, sCh, BT, accum);
}

extern "C" void kernel_launch(void* const* d_in, const int* in_sizes, int n_in,
                              void* d_out, int out_size)
{
    (void)in_sizes; (void)n_in; (void)out_size;
    const float* x     = (const float*)d_in[0];
    const float* cosp  = (const float*)d_in[1];
    const float* sinp  = (const float*)d_in[2];
    const float* W_dq  = (const float*)d_in[3];
    const float* W_uq  = (const float*)d_in[4];
    const float* W_dkv = (const float*)d_in[5];
    const float* W_uk  = (const float*)d_in[6];
    const float* W_uv  = (const float*)d_in[7];
    const float* W_qr  = (const float*)d_in[8];
    const float* W_kr  = (const float*)d_in[9];
    const float* W_o   = (const float*)d_in[10];
    float* y = (float*)d_out;

    float *cq, *ckv, *keff, *Rt, *qc, *cqr, *qr, *ckr, *kr, *S, *ctx;
    cudaGetSymbolAddress((void**)&cq,   g_cq);
    cudaGetSymbolAddress((void**)&ckv,  g_ckv);
    cudaGetSymbolAddress((void**)&keff, g_keff);
    cudaGetSymbolAddress((void**)&Rt,   g_Rt);
    cudaGetSymbolAddress((void**)&qc,   g_qc);
    cudaGetSymbolAddress((void**)&cqr,  g_cqr);
    cudaGetSymbolAddress((void**)&qr,   g_qr);
    cudaGetSymbolAddress((void**)&ckr,  g_ckr);
    cudaGetSymbolAddress((void**)&kr,   g_kr);
    cudaGetSymbolAddress((void**)&S,    g_S);
    cudaGetSymbolAddress((void**)&ctx,  g_ctx);

    const long long TT   = (long long)T_ * T_;          // 4194304
    const long long T512 = (long long)T_ * 512;         // 1048576

    // 1) c_q = x @ W_dq^T     [4096,512]
    launch_gemm(x, W_dq, cq, B_*T_, NLQ_, C_, C_, C_, NLQ_,
                1, 1, 0,0, 0,0, 0,0, /*BT=*/1, 0);
    // 2) c_kv = x @ W_dkv^T   [4096,512]
    launch_gemm(x, W_dkv, ckv, B_*T_, NLKV_, C_, C_, C_, NLKV_,
                1, 1, 0,0, 0,0, 0,0, 1, 0);
    // 3) k_eff[h] = W_uq_r[:,h,:] @ W_uk_r[h]   (16 batched, M=512,N=512,K=128)
    launch_gemm(W_uq, W_uk, keff, NLQ_, NLKV_, HS_, C_, NLKV_, NLKV_,
                NH_, NH_, 0, HS_, 0, (long long)HS_*NLKV_, 0, (long long)NLQ_*NLKV_, 0, 0);
    // 4) Rt = W_o @ W_uv      [2048,512]
    launch_gemm(W_o, W_uv, Rt, C_, NLKV_, C_, C_, NLKV_, NLKV_,
                1, 1, 0,0, 0,0, 0,0, 0, 0);
    // 5) q_c[b,h] = c_q[b] @ k_eff[h]   (32 batched, M=2048,N=512,K=512)
    launch_gemm(cq, keff, qc, T_, NLKV_, NLQ_, NLQ_, NLKV_, NLKV_,
                B_*NH_, NH_, T512, 0, 0, (long long)NLQ_*NLKV_, (long long)NH_*T512, T512, 0, 0);
    // 6) c_qr = c_q @ W_qr^T   [4096,1024]
    launch_gemm(cq, W_qr, cqr, B_*T_, NH_*DHR_, NLQ_, NLQ_, NLQ_, NH_*DHR_,
                1, 1, 0,0, 0,0, 0,0, 1, 0);
    // 7) q_r = rope(c_qr)
    {
        int n = B_ * T_ * NH_ * (DHR_ / 2);
        rope_q_kernel<<<(n + 255) / 256, 256>>>(cqr, qr, cosp, sinp);
    }
    // 8) c_kr = x @ W_kr^T     [4096,64]
    launch_gemm(x, W_kr, ckr, B_*T_, DHR_, C_, C_, C_, DHR_,
                1, 1, 0,0, 0,0, 0,0, 1, 0);
    // 9) k_r = rope(c_kr)
    {
        int n = B_ * T_ * (DHR_ / 2);
        rope_k_kernel<<<(n + 255) / 256, 256>>>(ckr, kr, cosp, sinp);
    }
    // 10) S = q_c @ c_kv^T     (32 batched, M=2048,N=2048,K=512)
    launch_gemm(qc, ckv, S, T_, T_, NLKV_, NLKV_, NLKV_, T_,
                B_*NH_, NH_, (long long)NH_*T512, T512, T512, 0,
                (long long)NH_*TT, TT, 1, 0);
    // 11) S += q_r @ k_r^T     (32 batched, M=2048,N=2048,K=64; A row stride 1024)
    launch_gemm(qr, kr, S, T_, T_, DHR_, NH_*DHR_, DHR_, T_,
                B_*NH_, NH_, (long long)T_*NH_*DHR_, DHR_, (long long)T_*DHR_, 0,
                (long long)NH_*TT, TT, 1, 1);
    // 12) causal softmax in place
    softmax_causal_kernel<<<B_*NH_*T_, 256>>>(S);
    // 13) ctx = P @ c_kv       (32 batched, M=2048,N=512,K=2048)
    launch_gemm(S, ckv, ctx, T_, NLKV_, T_, T_, NLKV_, NLKV_,
                B_*NH_, NH_, (long long)NH_*TT, TT, T512, 0,
                (long long)NH_*T512, T512, 0, 0);
    // 14) y[b,t,h*128+d] = ctx[b,h] @ Rt[h*128: , :]^T   (32 batched, M=2048,N=128,K=512)
    launch_gemm(ctx, Rt, y, T_, HS_, NLKV_, NLKV_, NLKV_, C_,
                B_*NH_, NH_, (long long)NH_*T512, T512, 0, (long long)HS_*NLKV_,
                (long long)T_*C_, HS_, 1, 0);
}